// round 13
// baseline (speedup 1.0000x reference)
#include <cuda_runtime.h>
#include <cuda_bf16.h>
#include <cuda_fp16.h>
#include <cstdint>
#include <cstddef>

#define D_MODEL 512
#define NHEADS  8
#define DEPTH   64
#define BATCH   2
#define SEQ     2048
#define MROWS   (BATCH*SEQ)   // 4096

#define LOG2E 1.4426950408889634f

// fp16 scratch (allocation-free rule: __device__ globals)
__device__ __half g_xh[MROWS * D_MODEL];   // x hi, later attn-out hi
__device__ __half g_xl[MROWS * D_MODEL];   // x lo, later attn-out lo
__device__ __half g_qf[MROWS * D_MODEL];   // Q single fp16
__device__ __half g_kf[MROWS * D_MODEL];   // K single fp16
__device__ __half g_vf[MROWS * D_MODEL];   // V single fp16
__device__ __half g_w [4 * D_MODEL * D_MODEL];  // Wq,Wk,Wv,Wo single fp16

__device__ __forceinline__ float fast_ex2(float x) {
    float y;
    asm("ex2.approx.ftz.f32 %0, %1;" : "=f"(y) : "f"(x));
    return y;
}
__device__ __forceinline__ uint32_t smem_u32(const void* p) {
    uint32_t a;
    asm("{ .reg .u64 t; cvta.to.shared.u64 t, %1; cvt.u32.u64 %0, t; }"
        : "=r"(a) : "l"(p));
    return a;
}
__device__ __forceinline__ uint32_t packh2(float lo, float hi) {
    __half2 h = __floats2half2_rn(lo, hi);
    uint32_t u; *(__half2*)&u = h; return u;
}
__device__ __forceinline__ float2 unpackh2(uint32_t u) {
    return __half22float2(*(__half2*)&u);
}

__device__ __forceinline__ void cp16(uint32_t s, const void* g) {
    asm volatile("cp.async.cg.shared.global [%0], [%1], 16;" :: "r"(s), "l"(g));
}
#define CP_COMMIT() asm volatile("cp.async.commit_group;" ::: "memory")
#define CP_WAIT(N)  asm volatile("cp.async.wait_group %0;" :: "n"(N) : "memory")

#define LDSM_X4(r0,r1,r2,r3,addr) \
    asm volatile("ldmatrix.sync.aligned.m8n8.x4.shared.b16 {%0,%1,%2,%3}, [%4];" \
                 : "=r"(r0), "=r"(r1), "=r"(r2), "=r"(r3) : "r"(addr))
#define LDSM_X4T(r0,r1,r2,r3,addr) \
    asm volatile("ldmatrix.sync.aligned.m8n8.x4.trans.shared.b16 {%0,%1,%2,%3}, [%4];" \
                 : "=r"(r0), "=r"(r1), "=r"(r2), "=r"(r3) : "r"(addr))
#define MMAH16816(d0,d1,d2,d3,a0,a1,a2,a3,b0,b1) \
    asm volatile("mma.sync.aligned.m16n8k16.row.col.f32.f16.f16.f32 " \
                 "{%0,%1,%2,%3}, {%4,%5,%6,%7}, {%8,%9}, {%0,%1,%2,%3};" \
                 : "+f"(d0), "+f"(d1), "+f"(d2), "+f"(d3) \
                 : "r"(a0), "r"(a1), "r"(a2), "r"(a3), "r"(b0), "r"(b1))

// ===========================================================================
// fp32 -> fp16 hi/lo split (x / activations)
// ===========================================================================
__global__ __launch_bounds__(256) void convert_hilo(
    const float* __restrict__ src, __half* __restrict__ h,
    __half* __restrict__ l, int n4)
{
    int i = blockIdx.x * blockDim.x + threadIdx.x;
    if (i >= n4) return;
    float4 f = ((const float4*)src)[i];
    uint32_t h01 = packh2(f.x, f.y);
    uint32_t h23 = packh2(f.z, f.w);
    float2 f01 = unpackh2(h01), f23 = unpackh2(h23);
    uint32_t l01 = packh2(f.x - f01.x, f.y - f01.y);
    uint32_t l23 = packh2(f.z - f23.x, f.w - f23.y);
    ((uint2*)h)[i] = make_uint2(h01, h23);
    ((uint2*)l)[i] = make_uint2(l01, l23);
}

// all 4 weights, single fp16, one launch
__global__ __launch_bounds__(256) void convert_w4(
    const float* __restrict__ w0, const float* __restrict__ w1,
    const float* __restrict__ w2, const float* __restrict__ w3,
    __half* __restrict__ w)
{
    const int n4 = D_MODEL * D_MODEL / 4;
    int i = blockIdx.x * blockDim.x + threadIdx.x;
    if (i >= n4) return;
    int y = blockIdx.y;
    const float* src = (y == 0) ? w0 : (y == 1) ? w1 : (y == 2) ? w2 : w3;
    size_t o = (size_t)y * n4 + i;
    float4 f = ((const float4*)src)[i];
    ((uint2*)w)[o] = make_uint2(packh2(f.x, f.y), packh2(f.z, f.w));
}

// ===========================================================================
// fp16 GEMM: out = (Ah[+Al])*W^T + bias.
// QKV projection (wsel<0): single-term (outputs quantized to fp16 anyway).
// O-projection (wsel>=0): 2-term Ah*W + Al*W, fp32 epilogue.
// cp.async 2-stage, fused QKV via grid.z. CTA 128x128, K-step 32, 256 thr.
// smem: 2 stages x 3 tiles x (128 x 80 B) = 61440 B.
// ===========================================================================
#define SROW 80
#define GTILE 10240
#define GSTAGE (3*GTILE)

__global__ __launch_bounds__(256) void gemm_mma(
    const __half* __restrict__ Ah, const __half* __restrict__ Al,
    const __half* __restrict__ Wb,
    const float* __restrict__ b0, const float* __restrict__ b1, const float* __restrict__ b2,
    __half* __restrict__ qf, __half* __restrict__ kf, __half* __restrict__ vf,
    float* __restrict__ outf, float alphaQ, int wsel)
{
    extern __shared__ __align__(16) char dsm[];
    const uint32_t sb = smem_u32(dsm);

    const int z = blockIdx.z;
    const bool use_lo = (wsel >= 0);                 // O-projection only
    const __half* W = Wb + (size_t)(wsel >= 0 ? wsel : z) * D_MODEL * D_MODEL;
    const float* bias = (z == 0) ? b0 : (z == 1) ? b1 : b2;
    const float alpha = (z == 0) ? alphaQ : 1.0f;

    const int tid = threadIdx.x;
    const int wid = tid >> 5, lane = tid & 31;
    const int wm = wid & 1, wn = wid >> 1;
    const int m0 = blockIdx.y * 128;
    const int n0 = blockIdx.x * 128;

    const int lrow = tid >> 1, lseg = tid & 1;
    const uint32_t soff = (uint32_t)lrow * SROW + (uint32_t)lseg * 32;
    const size_t ga_base = (size_t)(m0 + lrow) * D_MODEL + lseg * 16;
    const size_t gw_base = (size_t)(n0 + lrow) * D_MODEL + lseg * 16;

    const uint32_t a_row = (uint32_t)(wm * 64 + (lane & 7) + ((lane >> 3) & 1) * 8);
    const uint32_t a_colb = (uint32_t)((lane >> 4) * 16);
    const uint32_t b_row = (uint32_t)(wn * 32 + (lane & 7) + (lane >> 4) * 8);
    const uint32_t b_colb = (uint32_t)(((lane >> 3) & 1) * 16);

    float d[4][4][4];
    #pragma unroll
    for (int mi = 0; mi < 4; mi++)
        #pragma unroll
        for (int ni = 0; ni < 4; ni++)
            #pragma unroll
            for (int e = 0; e < 4; e++) d[mi][ni][e] = 0.f;

    auto issue = [&](int kc, int st) {
        const int k0 = kc * 32;
        const uint32_t S = sb + (uint32_t)st * GSTAGE;
        cp16(S + 0*GTILE + soff,      Ah + ga_base + k0);
        cp16(S + 0*GTILE + soff + 16, Ah + ga_base + k0 + 8);
        if (use_lo) {
            cp16(S + 1*GTILE + soff,      Al + ga_base + k0);
            cp16(S + 1*GTILE + soff + 16, Al + ga_base + k0 + 8);
        }
        cp16(S + 2*GTILE + soff,      W  + gw_base + k0);
        cp16(S + 2*GTILE + soff + 16, W  + gw_base + k0 + 8);
        CP_COMMIT();
    };

    issue(0, 0);
    const int NKC = D_MODEL / 32;   // 16
    for (int kc = 0; kc < NKC; kc++) {
        const int cur = kc & 1;
        __syncthreads();
        if (kc + 1 < NKC) { issue(kc + 1, cur ^ 1); CP_WAIT(1); }
        else              { CP_WAIT(0); }
        __syncthreads();

        const uint32_t S = sb + (uint32_t)cur * GSTAGE;
        #pragma unroll
        for (int ks = 0; ks < 2; ks++) {
            const uint32_t kb = (uint32_t)(ks * 32);
            uint32_t ah[4][4], al[4][4];
            #pragma unroll
            for (int mi = 0; mi < 4; mi++) {
                uint32_t addr = (a_row + mi * 16) * SROW + kb + a_colb;
                LDSM_X4(ah[mi][0], ah[mi][1], ah[mi][2], ah[mi][3], S + 0*GTILE + addr);
                if (use_lo)
                    LDSM_X4(al[mi][0], al[mi][1], al[mi][2], al[mi][3], S + 1*GTILE + addr);
            }
            uint32_t bw[4][2];
            #pragma unroll
            for (int nb = 0; nb < 2; nb++) {
                uint32_t addr = (b_row + nb * 16) * SROW + kb + b_colb;
                uint32_t t0, t1, t2, t3;
                LDSM_X4(t0, t1, t2, t3, S + 2*GTILE + addr);
                bw[2*nb][0] = t0; bw[2*nb][1] = t1;
                bw[2*nb+1][0] = t2; bw[2*nb+1][1] = t3;
            }
            #pragma unroll
            for (int mi = 0; mi < 4; mi++)
                #pragma unroll
                for (int ni = 0; ni < 4; ni++) {
                    MMAH16816(d[mi][ni][0], d[mi][ni][1], d[mi][ni][2], d[mi][ni][3],
                              ah[mi][0], ah[mi][1], ah[mi][2], ah[mi][3],
                              bw[ni][0], bw[ni][1]);
                    if (use_lo)
                        MMAH16816(d[mi][ni][0], d[mi][ni][1], d[mi][ni][2], d[mi][ni][3],
                                  al[mi][0], al[mi][1], al[mi][2], al[mi][3],
                                  bw[ni][0], bw[ni][1]);
                }
        }
    }

    #pragma unroll
    for (int mi = 0; mi < 4; mi++) {
        int mrow = m0 + wm * 64 + mi * 16 + (lane >> 2);
        #pragma unroll
        for (int ni = 0; ni < 4; ni++) {
            int ncol = n0 + wn * 32 + ni * 8 + (lane & 3) * 2;
            float bb0 = __ldg(bias + ncol), bb1 = __ldg(bias + ncol + 1);
            float v0 = (d[mi][ni][0] + bb0) * alpha;
            float v1 = (d[mi][ni][1] + bb1) * alpha;
            float v2 = (d[mi][ni][2] + bb0) * alpha;
            float v3 = (d[mi][ni][3] + bb1) * alpha;
            size_t e0 = (size_t)mrow * D_MODEL + ncol;
            size_t e1 = (size_t)(mrow + 8) * D_MODEL + ncol;
            if (outf) {
                *(float2*)&outf[e0] = make_float2(v0, v1);
                *(float2*)&outf[e1] = make_float2(v2, v3);
            } else {
                __half* dst = (z == 0) ? qf : (z == 1) ? kf : vf;
                ((uint32_t*)dst)[e0 >> 1] = packh2(v0, v1);
                ((uint32_t*)dst)[e1 >> 1] = packh2(v2, v3);
            }
        }
    }
}

// ===========================================================================
// Flash attention, all-fp16 single-term. 128 threads (4 warps, 32 q-rows),
// KV tile 64. S = Q*K (1 MMA). PV = P*V (1 MMA).
// cp.async 3-stage pipeline; stage = K + V = 18432 B; total 55296 B.
// Output written as fp16 hi/lo (O-projection consumes 2-term).
// ===========================================================================
#define ASTRIDE 72
#define ATILE_B (64*144)       // 9216
#define ASTAGE  (2*ATILE_B)    // 18432

__global__ __launch_bounds__(128) void attn_mma(
    const __half* __restrict__ Qf, const __half* __restrict__ Kf,
    const __half* __restrict__ Vf,
    __half* __restrict__ Oh, __half* __restrict__ Ol)
{
    extern __shared__ __align__(16) char dsm[];
    __half* sbuf = (__half*)dsm;
    const uint32_t sb = smem_u32(dsm);

    const int tid = threadIdx.x;
    const int wid = tid >> 5, lane = tid & 31;
    const int bh = blockIdx.y;
    const int b = bh >> 3, h = bh & 7;
    const int row0 = blockIdx.x * 128;
    const size_t qbase  = ((size_t)(b * SEQ + row0)) * D_MODEL + h * 64;
    const size_t kvbase = ((size_t)(b * SEQ)) * D_MODEL + h * 64;

    // ---- stage Q [128 x 64] fp16 = 1024 uint4 chunks (8 per thread) ----
    #pragma unroll
    for (int i = 0; i < 8; i++) {
        int lin = tid + i * 128;
        int r = lin >> 3, c = (lin & 7) * 8;
        *(uint4*)&sbuf[r * ASTRIDE + c] =
            *(const uint4*)&Qf[qbase + (size_t)r * D_MODEL + c];
    }
    __syncthreads();

    uint32_t qf[2][4][4];
    {
        uint32_t arow = (uint32_t)(wid * 32 + (lane & 7) + ((lane >> 3) & 1) * 8);
        uint32_t acol = (uint32_t)((lane >> 4) * 16);
        #pragma unroll
        for (int mi = 0; mi < 2; mi++)
            #pragma unroll
            for (int kc = 0; kc < 4; kc++) {
                uint32_t ad = sb + (arow + mi * 16) * 144 + kc * 32 + acol;
                LDSM_X4(qf[mi][kc][0], qf[mi][kc][1], qf[mi][kc][2], qf[mi][kc][3], ad);
            }
    }
    __syncthreads();   // Q region free for pipeline reuse

    float m_[2][2], l_[2][2], o[2][8][4];
    #pragma unroll
    for (int mi = 0; mi < 2; mi++) {
        m_[mi][0] = m_[mi][1] = -3.0e38f;
        l_[mi][0] = l_[mi][1] = 0.f;
        #pragma unroll
        for (int nd = 0; nd < 8; nd++)
            #pragma unroll
            for (int e = 0; e < 4; e++) o[mi][nd][e] = 0.f;
    }

    auto issue = [&](int t, int st) {
        const uint32_t S = sb + (uint32_t)st * ASTAGE;
        #pragma unroll
        for (int i = 0; i < 4; i++) {
            int lin = tid + i * 128;
            int r = lin >> 3, c = (lin & 7) * 8;
            size_t g = kvbase + (size_t)(t * 64 + r) * D_MODEL + c;
            uint32_t so = (uint32_t)(r * 144 + c * 2);
            cp16(S + 0*ATILE_B + so, Kf + g);
            cp16(S + 1*ATILE_B + so, Vf + g);
        }
        CP_COMMIT();
    };

    const int NT = SEQ / 64;   // 32
    issue(0, 0);
    issue(1, 1);
    for (int it = 0; it < NT; it++) {
        const int cur = it - (it / 3) * 3;   // it % 3
        __syncthreads();
        if (it + 2 < NT) { issue(it + 2, (it + 2) - ((it + 2) / 3) * 3); CP_WAIT(2); }
        else if (it + 1 < NT) { CP_WAIT(1); }
        else { CP_WAIT(0); }
        __syncthreads();

        const uint32_t S_K = sb + (uint32_t)cur * ASTAGE;
        const uint32_t S_V = S_K + ATILE_B;

        // ---- S = Q K^T (single fp16 term) ----
        float s[2][8][4];
        #pragma unroll
        for (int mi = 0; mi < 2; mi++)
            #pragma unroll
            for (int ni = 0; ni < 8; ni++)
                #pragma unroll
                for (int e = 0; e < 4; e++) s[mi][ni][e] = 0.f;

        #pragma unroll
        for (int kc = 0; kc < 4; kc++) {
            uint32_t kb[8][2];
            uint32_t brow = (uint32_t)((lane & 7) + (lane >> 4) * 8);
            uint32_t bcol = (uint32_t)(kc * 32 + ((lane >> 3) & 1) * 16);
            #pragma unroll
            for (int nb = 0; nb < 4; nb++) {
                uint32_t ad = (brow + nb * 16) * 144 + bcol;
                uint32_t t0, t1, t2, t3;
                LDSM_X4(t0, t1, t2, t3, S_K + ad);
                kb[2*nb][0] = t0; kb[2*nb][1] = t1;
                kb[2*nb+1][0] = t2; kb[2*nb+1][1] = t3;
            }
            #pragma unroll
            for (int mi = 0; mi < 2; mi++)
                #pragma unroll
                for (int ni = 0; ni < 8; ni++)
                    MMAH16816(s[mi][ni][0], s[mi][ni][1], s[mi][ni][2], s[mi][ni][3],
                              qf[mi][kc][0], qf[mi][kc][1], qf[mi][kc][2], qf[mi][kc][3],
                              kb[ni][0], kb[ni][1]);
        }

        // ---- online softmax; P packed as single fp16 ----
        uint32_t ph0[2][8], ph1[2][8];
        #pragma unroll
        for (int mi = 0; mi < 2; mi++) {
            float mx0 = -3.0e38f, mx1 = -3.0e38f;
            #pragma unroll
            for (int ni = 0; ni < 8; ni++) {
                mx0 = fmaxf(mx0, fmaxf(s[mi][ni][0], s[mi][ni][1]));
                mx1 = fmaxf(mx1, fmaxf(s[mi][ni][2], s[mi][ni][3]));
            }
            mx0 = fmaxf(mx0, __shfl_xor_sync(0xffffffffu, mx0, 1));
            mx0 = fmaxf(mx0, __shfl_xor_sync(0xffffffffu, mx0, 2));
            mx1 = fmaxf(mx1, __shfl_xor_sync(0xffffffffu, mx1, 1));
            mx1 = fmaxf(mx1, __shfl_xor_sync(0xffffffffu, mx1, 2));
            float mn0 = fmaxf(m_[mi][0], mx0);
            float mn1 = fmaxf(m_[mi][1], mx1);
            float c0 = fast_ex2(m_[mi][0] - mn0);
            float c1 = fast_ex2(m_[mi][1] - mn1);
            m_[mi][0] = mn0; m_[mi][1] = mn1;
            float s0 = 0.f, s1 = 0.f;
            #pragma unroll
            for (int ni = 0; ni < 8; ni++) {
                float p0 = fast_ex2(s[mi][ni][0] - mn0);
                float p1 = fast_ex2(s[mi][ni][1] - mn0);
                float p2 = fast_ex2(s[mi][ni][2] - mn1);
                float p3 = fast_ex2(s[mi][ni][3] - mn1);
                s0 += p0 + p1; s1 += p2 + p3;
                ph0[mi][ni] = packh2(p0, p1);
                ph1[mi][ni] = packh2(p2, p3);
            }
            s0 += __shfl_xor_sync(0xffffffffu, s0, 1);
            s0 += __shfl_xor_sync(0xffffffffu, s0, 2);
            s1 += __shfl_xor_sync(0xffffffffu, s1, 1);
            s1 += __shfl_xor_sync(0xffffffffu, s1, 2);
            l_[mi][0] = l_[mi][0] * c0 + s0;
            l_[mi][1] = l_[mi][1] * c1 + s1;
            #pragma unroll
            for (int nd = 0; nd < 8; nd++) {
                o[mi][nd][0] *= c0; o[mi][nd][1] *= c0;
                o[mi][nd][2] *= c1; o[mi][nd][3] *= c1;
            }
        }

        // ---- O += P V (single fp16 term) ----
        #pragma unroll
        for (int kt = 0; kt < 4; kt++) {
            uint32_t vb[8][2];
            uint32_t vrow = (uint32_t)(kt * 16 + (lane & 7) + ((lane >> 3) & 1) * 8);
            #pragma unroll
            for (int np = 0; np < 4; np++) {
                uint32_t ad = vrow * 144 + (uint32_t)(np * 32 + (lane >> 4) * 16);
                uint32_t t0, t1, t2, t3;
                LDSM_X4T(t0, t1, t2, t3, S_V + ad);
                vb[2*np][0] = t0; vb[2*np][1] = t1;
                vb[2*np+1][0] = t2; vb[2*np+1][1] = t3;
            }
            #pragma unroll
            for (int mi = 0; mi < 2; mi++) {
                uint32_t a0 = ph0[mi][2*kt],   a1 = ph1[mi][2*kt];
                uint32_t a2 = ph0[mi][2*kt+1], a3 = ph1[mi][2*kt+1];
                #pragma unroll
                for (int nd = 0; nd < 8; nd++)
                    MMAH16816(o[mi][nd][0], o[mi][nd][1], o[mi][nd][2], o[mi][nd][3],
                              a0, a1, a2, a3, vb[nd][0], vb[nd][1]);
            }
        }
    }

    // ---- normalize, split fp16 hi/lo, store ----
    #pragma unroll
    for (int mi = 0; mi < 2; mi++)
        #pragma unroll
        for (int hh = 0; hh < 2; hh++) {
            float inv = 1.f / l_[mi][hh];
            int r = row0 + wid * 32 + mi * 16 + (lane >> 2) + hh * 8;
            size_t base = ((size_t)(b * SEQ + r)) * D_MODEL + h * 64 + (lane & 3) * 2;
            #pragma unroll
            for (int nd = 0; nd < 8; nd++) {
                float v0 = o[mi][nd][2*hh]     * inv;
                float v1 = o[mi][nd][2*hh + 1] * inv;
                uint32_t hp = packh2(v0, v1);
                float2 fp = unpackh2(hp);
                uint32_t lp = packh2(v0 - fp.x, v1 - fp.y);
                size_t e = base + nd * 8;
                ((uint32_t*)Oh)[e >> 1] = hp;
                ((uint32_t*)Ol)[e >> 1] = lp;
            }
        }
}

// ---------------------------------------------------------------------------
extern "C" void kernel_launch(void* const* d_in, const int* in_sizes, int n_in,
                              void* d_out, int out_size)
{
    const float* x  = (const float*)d_in[0];
    const float* Wq = (const float*)d_in[1];
    const float* bq = (const float*)d_in[2];
    const float* Wk = (const float*)d_in[3];
    const float* bk = (const float*)d_in[4];
    const float* Wv = (const float*)d_in[5];
    const float* bv = (const float*)d_in[6];
    const float* Wo = (const float*)d_in[7];
    const float* bo = (const float*)d_in[8];
    float* out = (float*)d_out;

    __half *xh, *xl, *qf, *kf, *vf, *w;
    cudaGetSymbolAddress((void**)&xh, g_xh);
    cudaGetSymbolAddress((void**)&xl, g_xl);
    cudaGetSymbolAddress((void**)&qf, g_qf);
    cudaGetSymbolAddress((void**)&kf, g_kf);
    cudaGetSymbolAddress((void**)&vf, g_vf);
    cudaGetSymbolAddress((void**)&w,  g_w);

    const int xn4 = MROWS * D_MODEL / 4;
    const int wn4 = D_MODEL * D_MODEL / 4;

    const int gemm_smem = 2 * GSTAGE;   // 61440
    const int attn_smem = 3 * ASTAGE;   // 55296
    cudaFuncSetAttribute(gemm_mma,
                         cudaFuncAttributeMaxDynamicSharedMemorySize, gemm_smem);
    cudaFuncSetAttribute(attn_mma,
                         cudaFuncAttributeMaxDynamicSharedMemorySize, attn_smem);

    convert_hilo<<<xn4 / 256, 256>>>(x, xh, xl, xn4);
    convert_w4<<<dim3(wn4 / 256, 4), 256>>>(Wq, Wk, Wv, Wo, w);

    // fused QKV projection, single-term (outputs all single fp16)
    gemm_mma<<<dim3(D_MODEL / 128, MROWS / 128, 3), 256, gemm_smem>>>(
        xh, xl, w, bq, bk, bv, qf, kf, vf, nullptr, 0.125f * LOG2E, -1);

    // attention (writes fp16 hi/lo into xh/xl; x is dead)
    attn_mma<<<dim3(SEQ / 128, BATCH * NHEADS), 128, attn_smem>>>(
        qf, kf, vf, xh, xl);

    // output projection (weight slot 3 = Wo), 2-term, fp32 epilogue
    gemm_mma<<<dim3(D_MODEL / 128, MROWS / 128, 1), 256, gemm_smem>>>(
        xh, xl, w, bo, nullptr, nullptr, nullptr, nullptr, nullptr,
        out, 1.0f, 3);
}